// round 4
// baseline (speedup 1.0000x reference)
#include <cuda_runtime.h>
#include <math.h>

#define BB 4096
#define DD 128
#define TT 5
#define G4 512   // 4 gates * D

// Scratch state (allocation-free: device globals)
__device__ float g_xg[BB * TT * G4];   // precomputed input-gate terms (+bias)
__device__ float g_gates[BB * G4];     // per-step gate preactivations
__device__ float g_h[BB * DD];
__device__ float g_c[BB * DD];

#define MT 128
#define NT 64
#define KC 32

// C[M,N] = A[M,K] * W[N,K]^T (+ bias | + xg), A rows gathered via pointer table.
// mode 0: xg GEMM (A = gathered seq rows, epilogue adds b_ih+b_hh, writes g_xg)
// mode 1: recurrence GEMM (A = g_h, epilogue adds g_xg[:,t,:], writes g_gates)
__global__ __launch_bounds__(256) void gemm_kernel(
    const float* __restrict__ Wmat,
    const int* __restrict__ pos_r,
    const int* __restrict__ pos_tem,
    const float* __restrict__ rel_emb,
    const float* __restrict__ tem_emb,
    const float* __restrict__ b_ih,
    const float* __restrict__ b_hh,
    int mode, int t)
{
    __shared__ float As[KC][MT + 4];
    __shared__ float Bs[KC][NT + 4];
    __shared__ const float* rowptr[MT];
    __shared__ float bias_s[NT];

    const int tid = threadIdx.x;
    const int bm = blockIdx.x;
    const int bn = blockIdx.y;
    const int ncol0 = bn * NT;

    if (tid < MT) {
        int m = bm * MT + tid;
        const float* p;
        if (mode == 0) {
            int b  = m / TT;
            int tt = m - b * TT;
            if (tt == 0) p = rel_emb + (size_t)pos_r[b] * DD;
            else         p = tem_emb + (size_t)pos_tem[b * 4 + tt - 1] * DD;
        } else {
            p = g_h + (size_t)m * DD;
        }
        rowptr[tid] = p;
    }
    if (mode == 0 && tid < NT)
        bias_s[tid] = b_ih[ncol0 + tid] + b_hh[ncol0 + tid];

    float acc[8][4];
#pragma unroll
    for (int r = 0; r < 8; r++)
#pragma unroll
        for (int c = 0; c < 4; c++) acc[r][c] = 0.f;

    const int ty = tid >> 4;      // 0..15
    const int tx = tid & 15;      // 0..15
    const int row0 = ty * 8;
    const int col0 = tx * 4;

    __syncthreads();   // rowptr / bias ready

    for (int k0 = 0; k0 < DD; k0 += KC) {
        // Load A tile (gathered rows), transposed into As[k][row]
#pragma unroll
        for (int j = 0; j < 4; j++) {
            int f4i = tid * 4 + j;          // 0..1023
            int row = f4i >> 3;             // 0..127
            int kk  = (f4i & 7) << 2;       // 0,4,..,28
            float4 v = *(const float4*)(rowptr[row] + k0 + kk);
            As[kk + 0][row] = v.x; As[kk + 1][row] = v.y;
            As[kk + 2][row] = v.z; As[kk + 3][row] = v.w;
        }
        // Load W tile, transposed into Bs[k][col]
#pragma unroll
        for (int j = 0; j < 2; j++) {
            int f4i = tid * 2 + j;          // 0..511
            int col = f4i >> 3;             // 0..63
            int kk  = (f4i & 7) << 2;
            float4 v = *(const float4*)(Wmat + (size_t)(ncol0 + col) * DD + k0 + kk);
            Bs[kk + 0][col] = v.x; Bs[kk + 1][col] = v.y;
            Bs[kk + 2][col] = v.z; Bs[kk + 3][col] = v.w;
        }
        __syncthreads();

#pragma unroll
        for (int k = 0; k < KC; k++) {
            float4 a0 = *(const float4*)&As[k][row0];
            float4 a1 = *(const float4*)&As[k][row0 + 4];
            float4 bv = *(const float4*)&Bs[k][col0];
            float a[8]  = {a0.x, a0.y, a0.z, a0.w, a1.x, a1.y, a1.z, a1.w};
            float bb[4] = {bv.x, bv.y, bv.z, bv.w};
#pragma unroll
            for (int r = 0; r < 8; r++)
#pragma unroll
                for (int c = 0; c < 4; c++)
                    acc[r][c] = fmaf(a[r], bb[c], acc[r][c]);
        }
        __syncthreads();
    }

#pragma unroll
    for (int r = 0; r < 8; r++) {
        int m = bm * MT + row0 + r;
        float4 o;
        if (mode == 0) {
            o.x = acc[r][0] + bias_s[col0 + 0];
            o.y = acc[r][1] + bias_s[col0 + 1];
            o.z = acc[r][2] + bias_s[col0 + 2];
            o.w = acc[r][3] + bias_s[col0 + 3];
            *(float4*)&g_xg[(size_t)m * G4 + ncol0 + col0] = o;
        } else {
            float4 x = *(const float4*)&g_xg[((size_t)m * TT + t) * G4 + ncol0 + col0];
            o.x = acc[r][0] + x.x;
            o.y = acc[r][1] + x.y;
            o.z = acc[r][2] + x.z;
            o.w = acc[r][3] + x.w;
            *(float4*)&g_gates[(size_t)m * G4 + ncol0 + col0] = o;
        }
    }
}

__device__ __forceinline__ float sigmoidf_(float x) {
    return 1.f / (1.f + expf(-x));
}

// Step 0: h_prev = c_prev = 0 -> gates come straight from g_xg[:,0,:]
__global__ __launch_bounds__(256) void lstm_step0_kernel()
{
    int idx = blockIdx.x * blockDim.x + threadIdx.x;
    if (idx >= BB * DD) return;
    int b = idx >> 7;
    int j = idx & (DD - 1);
    const float* g = g_xg + (size_t)b * TT * G4;   // t = 0
    float i  = sigmoidf_(g[j]);
    float gg = tanhf(g[2 * DD + j]);
    float o  = sigmoidf_(g[3 * DD + j]);
    float c  = i * gg;                              // f*0 + i*g
    g_c[idx] = c;
    g_h[idx] = o * tanhf(c);
}

__global__ __launch_bounds__(256) void lstm_step_kernel()
{
    int idx = blockIdx.x * blockDim.x + threadIdx.x;
    if (idx >= BB * DD) return;
    int b = idx >> 7;
    int j = idx & (DD - 1);
    const float* g = g_gates + (size_t)b * G4;
    float i  = sigmoidf_(g[j]);
    float f  = sigmoidf_(g[DD + j]);
    float gg = tanhf(g[2 * DD + j]);
    float o  = sigmoidf_(g[3 * DD + j]);
    float c  = f * g_c[idx] + i * gg;
    g_c[idx] = c;
    g_h[idx] = o * tanhf(c);
}

// One warp per batch row; pos and neg share h (matches reference's use of pos_rseq for both)
__global__ __launch_bounds__(256) void score_kernel(
    const int* __restrict__ pos_h, const int* __restrict__ pos_t,
    const int* __restrict__ neg_h, const int* __restrict__ neg_t,
    const float* __restrict__ ent, float* __restrict__ out)
{
    int gw   = (blockIdx.x * blockDim.x + threadIdx.x) >> 5;
    int lane = threadIdx.x & 31;
    if (gw >= BB) return;

    const float4* ph = (const float4*)(ent + (size_t)pos_h[gw] * DD);
    const float4* pt = (const float4*)(ent + (size_t)pos_t[gw] * DD);
    const float4* nh = (const float4*)(ent + (size_t)neg_h[gw] * DD);
    const float4* nt = (const float4*)(ent + (size_t)neg_t[gw] * DD);
    const float4* hh = (const float4*)(g_h + (size_t)gw * DD);

    float4 h4 = hh[lane];
    float4 a  = ph[lane];
    float4 b4 = pt[lane];
    float pos = fabsf(a.x + h4.x - b4.x) + fabsf(a.y + h4.y - b4.y)
              + fabsf(a.z + h4.z - b4.z) + fabsf(a.w + h4.w - b4.w);
    a  = nh[lane];
    b4 = nt[lane];
    float neg = fabsf(a.x + h4.x - b4.x) + fabsf(a.y + h4.y - b4.y)
              + fabsf(a.z + h4.z - b4.z) + fabsf(a.w + h4.w - b4.w);

#pragma unroll
    for (int off = 16; off; off >>= 1) {
        pos += __shfl_down_sync(0xffffffffu, pos, off);
        neg += __shfl_down_sync(0xffffffffu, neg, off);
    }
    if (lane == 0) {
        out[gw]      = pos;
        out[BB + gw] = neg;
    }
}

extern "C" void kernel_launch(void* const* d_in, const int* in_sizes, int n_in,
                              void* d_out, int out_size)
{
    (void)in_sizes; (void)n_in; (void)out_size;
    const int*   pos_h   = (const int*)d_in[0];
    const int*   pos_t   = (const int*)d_in[1];
    const int*   pos_r   = (const int*)d_in[2];
    const int*   pos_tem = (const int*)d_in[3];
    const int*   neg_h   = (const int*)d_in[4];
    const int*   neg_t   = (const int*)d_in[5];
    // d_in[6] neg_r, d_in[7] neg_tem: unused by reference score
    const float* ent     = (const float*)d_in[8];
    const float* rel     = (const float*)d_in[9];
    const float* tem     = (const float*)d_in[10];
    const float* W_ih    = (const float*)d_in[11];
    const float* W_hh    = (const float*)d_in[12];
    const float* b_ih    = (const float*)d_in[13];
    const float* b_hh    = (const float*)d_in[14];
    float* out = (float*)d_out;

    // 1) xg = seq @ W_ih^T + (b_ih + b_hh), seq gathered from rel/tem embeddings
    dim3 gxg(BB * TT / MT, G4 / NT);   // 160 x 8
    gemm_kernel<<<gxg, 256>>>(W_ih, pos_r, pos_tem, rel, tem, b_ih, b_hh, 0, 0);

    // 2) LSTM step 0 (h_prev = c_prev = 0: no GEMM needed)
    lstm_step0_kernel<<<(BB * DD) / 256, 256>>>();

    // 3) Steps 1..4: gates = xg[:,t,:] + h @ W_hh^T, then update
    dim3 grec(BB / MT, G4 / NT);       // 32 x 8
    for (int t = 1; t < TT; t++) {
        gemm_kernel<<<grec, 256>>>(W_hh, pos_r, pos_tem, rel, tem, b_ih, b_hh, 1, t);
        lstm_step_kernel<<<(BB * DD) / 256, 256>>>();
    }

    // 4) L1 scores
    score_kernel<<<(BB * 32) / 256, 256>>>(pos_h, pos_t, neg_h, neg_t, ent, out);
}

// round 6
// speedup vs baseline: 1.4152x; 1.4152x over previous
#include <cuda_runtime.h>
#include <math.h>

#define BB 4096
#define DD 128
#define TT 5
#define G4 512          // 4 gates * D
#define NPROJ 532       // 500 rel rows + 32 tem rows

// Scratch (allocation-free: device globals)
__device__ float g_proj[NPROJ * G4];   // [rel;tem] @ W_ih^T + b   (L2-resident, ~1MB)
__device__ float g_h[BB * DD];
__device__ float g_c[BB * DD];

__device__ __forceinline__ float sigmoidf_(float x) {
    return 1.f / (1.f + expf(-x));
}

// ---------------------------------------------------------------------------
// proj_kernel: g_proj[r][c] = emb_row(r) . W_ih[c] + b_ih[c] + b_hh[c]
// rows 0..499 = rel_emb, rows 500..531 = tem_emb.  ~35 MMAC total.
// grid (17, 16), block 256. Tile: 32 rows x 32 cols, full K=128 in smem.
// ---------------------------------------------------------------------------
__global__ __launch_bounds__(256) void proj_kernel(
    const float* __restrict__ W_ih,
    const float* __restrict__ rel_emb,
    const float* __restrict__ tem_emb,
    const float* __restrict__ b_ih,
    const float* __restrict__ b_hh)
{
    __shared__ float As[DD][36];          // [k][row], row<32
    __shared__ float Bs[DD][36];          // [k][col], col<32
    __shared__ const float* rowptr[32];

    const int tid = threadIdx.x;
    const int m0 = blockIdx.x * 32;
    const int n0 = blockIdx.y * 32;

    if (tid < 32) {
        int r = m0 + tid;
        if (r >= NPROJ) r = 0;            // clamp for safe load; store guarded
        rowptr[tid] = (r < 500) ? (rel_emb + (size_t)r * DD)
                                : (tem_emb + (size_t)(r - 500) * DD);
    }
    __syncthreads();

#pragma unroll
    for (int q = 0; q < 4; q++) {         // A: 32x128 = 1024 float4
        int f4i = tid * 4 + q;
        int row = f4i >> 5;
        int kk  = (f4i & 31) << 2;
        float4 v = *(const float4*)(rowptr[row] + kk);
        As[kk + 0][row] = v.x; As[kk + 1][row] = v.y;
        As[kk + 2][row] = v.z; As[kk + 3][row] = v.w;
    }
#pragma unroll
    for (int q = 0; q < 4; q++) {         // B: 32x128 = 1024 float4
        int f4i = tid * 4 + q;
        int col = f4i >> 5;
        int kk  = (f4i & 31) << 2;
        float4 v = *(const float4*)(W_ih + (size_t)(n0 + col) * DD + kk);
        Bs[kk + 0][col] = v.x; Bs[kk + 1][col] = v.y;
        Bs[kk + 2][col] = v.z; Bs[kk + 3][col] = v.w;
    }
    __syncthreads();

    const int ty = tid >> 4;              // 0..15 -> 2 rows each
    const int tx = tid & 15;              // 0..15 -> 2 cols each
    const int row0 = ty * 2;
    const int col0 = tx * 2;

    float acc[2][2] = {{0.f, 0.f}, {0.f, 0.f}};
#pragma unroll
    for (int k = 0; k < DD; k++) {
        float a0 = As[k][row0], a1 = As[k][row0 + 1];
        float2 b = *(const float2*)&Bs[k][col0];  // stride 36 floats: 8B aligned
        acc[0][0] = fmaf(a0, b.x, acc[0][0]);
        acc[0][1] = fmaf(a0, b.y, acc[0][1]);
        acc[1][0] = fmaf(a1, b.x, acc[1][0]);
        acc[1][1] = fmaf(a1, b.y, acc[1][1]);
    }

    float bia0 = b_ih[n0 + col0]     + b_hh[n0 + col0];
    float bia1 = b_ih[n0 + col0 + 1] + b_hh[n0 + col0 + 1];
#pragma unroll
    for (int r = 0; r < 2; r++) {
        int m = m0 + row0 + r;
        if (m < NPROJ) {
            float2 o = {acc[r][0] + bia0, acc[r][1] + bia1};
            *(float2*)&g_proj[(size_t)m * G4 + n0 + col0] = o;
        }
    }
}

// ---------------------------------------------------------------------------
// Step 0: h_prev = c_prev = 0, gates = g_proj[pos_r[b]] (rel projection).
// c = sig(i)*tanh(g);  h = sig(o)*tanh(c).  (f*0 drops out)
// ---------------------------------------------------------------------------
__global__ __launch_bounds__(256) void lstm_step0_kernel(const int* __restrict__ pos_r)
{
    int idx = blockIdx.x * blockDim.x + threadIdx.x;
    if (idx >= BB * DD) return;
    int b = idx >> 7;
    int j = idx & (DD - 1);
    const float* g = g_proj + (size_t)pos_r[b] * G4;
    float i  = sigmoidf_(g[j]);
    float gg = tanhf(g[2 * DD + j]);
    float o  = sigmoidf_(g[3 * DD + j]);
    float c  = i * gg;
    g_c[idx] = c;
    g_h[idx] = o * tanhf(c);
}

// ---------------------------------------------------------------------------
// rec_step_kernel (t = 1..4):
//   gates[b] = g_proj[500 + pos_tem[b][t-1]] + h[b] @ W_hh^T   (fused epilogue
//   applies sigmoid/tanh and writes h, c directly; no gate round-trip)
// grid 128 (BB/32), block 256. Tile 32 rows x 512 cols, K=128 chunked by 8.
// Thread (ty=tid/64, tx=tid%64): rows ty*8..+7, j in {2tx, 2tx+1}, all 4 gates.
// ---------------------------------------------------------------------------
#define KC 8
__global__ __launch_bounds__(256) void rec_step_kernel(
    const float* __restrict__ W_hh,
    const int*   __restrict__ pos_tem,
    int t)
{
    __shared__ float As[DD][36];     // h tile transposed [k][row]   (18.4KB)
    __shared__ float Bs[KC][516];    // W_hh chunk [k][col]          (16.5KB)
    __shared__ int   temrow[32];     // proj row index per batch row

    const int tid = threadIdx.x;
    const int m0  = blockIdx.x * 32;
    const int tx  = tid & 63;        // j0 = 2*tx
    const int ty  = tid >> 6;        // rows ty*8..ty*8+7
    const int row0 = ty * 8;
    const int j0   = 2 * tx;

    if (tid < 32)
        temrow[tid] = 500 + pos_tem[(m0 + tid) * 4 + (t - 1)];

    // Load A (h tile): 32 rows x 128 k = 1024 float4, 4/thread, transposed
#pragma unroll
    for (int q = 0; q < 4; q++) {
        int f4i = tid * 4 + q;
        int row = f4i >> 5;
        int kk  = (f4i & 31) << 2;
        float4 v = *(const float4*)(g_h + (size_t)(m0 + row) * DD + kk);
        As[kk + 0][row] = v.x; As[kk + 1][row] = v.y;
        As[kk + 2][row] = v.z; As[kk + 3][row] = v.w;
    }

    float acc[8][8];                 // acc[rr][g*2 + jj]
#pragma unroll
    for (int r = 0; r < 8; r++)
#pragma unroll
        for (int c = 0; c < 8; c++) acc[r][c] = 0.f;

    // B prefetch: per chunk 512x8 = 1024 float4, 4/thread
    float4 bv[4];
#pragma unroll
    for (int q = 0; q < 4; q++) {
        int col = (tid * 4 + q) >> 1;
        int kq  = (tid * 4 + q) & 1;
        bv[q] = *(const float4*)(W_hh + (size_t)col * DD + 4 * kq);
    }

    for (int ch = 0; ch < DD / KC; ch++) {
        __syncthreads();                       // prev chunk consumed / A ready
#pragma unroll
        for (int q = 0; q < 4; q++) {
            int col = (tid * 4 + q) >> 1;
            int kk  = ((tid * 4 + q) & 1) * 4;
            Bs[kk + 0][col] = bv[q].x; Bs[kk + 1][col] = bv[q].y;
            Bs[kk + 2][col] = bv[q].z; Bs[kk + 3][col] = bv[q].w;
        }
        __syncthreads();
        if (ch < DD / KC - 1) {
            int k0 = (ch + 1) * KC;
#pragma unroll
            for (int q = 0; q < 4; q++) {
                int col = (tid * 4 + q) >> 1;
                int kq  = (tid * 4 + q) & 1;
                bv[q] = *(const float4*)(W_hh + (size_t)col * DD + k0 + 4 * kq);
            }
        }
#pragma unroll
        for (int kk = 0; kk < KC; kk++) {
            int k = ch * KC + kk;
            float4 a0 = *(const float4*)&As[k][row0];       // 144B stride: aligned
            float4 a1 = *(const float4*)&As[k][row0 + 4];
            float a[8] = {a0.x, a0.y, a0.z, a0.w, a1.x, a1.y, a1.z, a1.w};
#pragma unroll
            for (int g = 0; g < 4; g++) {
                float2 b2 = *(const float2*)&Bs[kk][g * DD + j0];
#pragma unroll
                for (int rr = 0; rr < 8; rr++) {
                    acc[rr][g * 2 + 0] = fmaf(a[rr], b2.x, acc[rr][g * 2 + 0]);
                    acc[rr][g * 2 + 1] = fmaf(a[rr], b2.y, acc[rr][g * 2 + 1]);
                }
            }
        }
    }

    // Fused LSTM epilogue: add gathered x-projection, activate, update h/c.
#pragma unroll
    for (int rr = 0; rr < 8; rr++) {
        int m = m0 + row0 + rr;
        const float* p = g_proj + (size_t)temrow[row0 + rr] * G4;
        float2 pi = *(const float2*)(p + j0);
        float2 pf = *(const float2*)(p + DD + j0);
        float2 pg = *(const float2*)(p + 2 * DD + j0);
        float2 po = *(const float2*)(p + 3 * DD + j0);
        float2 co = *(const float2*)(g_c + (size_t)m * DD + j0);

        float i0 = sigmoidf_(acc[rr][0] + pi.x);
        float i1 = sigmoidf_(acc[rr][1] + pi.y);
        float f0 = sigmoidf_(acc[rr][2] + pf.x);
        float f1 = sigmoidf_(acc[rr][3] + pf.y);
        float g0 = tanhf(acc[rr][4] + pg.x);
        float g1 = tanhf(acc[rr][5] + pg.y);
        float o0 = sigmoidf_(acc[rr][6] + po.x);
        float o1 = sigmoidf_(acc[rr][7] + po.y);

        float c0 = f0 * co.x + i0 * g0;
        float c1 = f1 * co.y + i1 * g1;
        float2 cv = {c0, c1};
        float2 hv = {o0 * tanhf(c0), o1 * tanhf(c1)};
        *(float2*)(g_c + (size_t)m * DD + j0) = cv;
        *(float2*)(g_h + (size_t)m * DD + j0) = hv;
    }
}

// ---------------------------------------------------------------------------
// Score: one warp per batch row; pos and neg share pos_rseq h (per reference).
// ---------------------------------------------------------------------------
__global__ __launch_bounds__(256) void score_kernel(
    const int* __restrict__ pos_h, const int* __restrict__ pos_t,
    const int* __restrict__ neg_h, const int* __restrict__ neg_t,
    const float* __restrict__ ent, float* __restrict__ out)
{
    int gw   = (blockIdx.x * blockDim.x + threadIdx.x) >> 5;
    int lane = threadIdx.x & 31;
    if (gw >= BB) return;

    const float4* ph = (const float4*)(ent + (size_t)pos_h[gw] * DD);
    const float4* pt = (const float4*)(ent + (size_t)pos_t[gw] * DD);
    const float4* nh = (const float4*)(ent + (size_t)neg_h[gw] * DD);
    const float4* nt = (const float4*)(ent + (size_t)neg_t[gw] * DD);
    const float4* hh = (const float4*)(g_h + (size_t)gw * DD);

    float4 h4 = hh[lane];
    float4 a  = ph[lane];
    float4 b4 = pt[lane];
    float pos = fabsf(a.x + h4.x - b4.x) + fabsf(a.y + h4.y - b4.y)
              + fabsf(a.z + h4.z - b4.z) + fabsf(a.w + h4.w - b4.w);
    a  = nh[lane];
    b4 = nt[lane];
    float neg = fabsf(a.x + h4.x - b4.x) + fabsf(a.y + h4.y - b4.y)
              + fabsf(a.z + h4.z - b4.z) + fabsf(a.w + h4.w - b4.w);

#pragma unroll
    for (int off = 16; off; off >>= 1) {
        pos += __shfl_down_sync(0xffffffffu, pos, off);
        neg += __shfl_down_sync(0xffffffffu, neg, off);
    }
    if (lane == 0) {
        out[gw]      = pos;
        out[BB + gw] = neg;
    }
}

extern "C" void kernel_launch(void* const* d_in, const int* in_sizes, int n_in,
                              void* d_out, int out_size)
{
    (void)in_sizes; (void)n_in; (void)out_size;
    const int*   pos_h   = (const int*)d_in[0];
    const int*   pos_t   = (const int*)d_in[1];
    const int*   pos_r   = (const int*)d_in[2];
    const int*   pos_tem = (const int*)d_in[3];
    const int*   neg_h   = (const int*)d_in[4];
    const int*   neg_t   = (const int*)d_in[5];
    // d_in[6] neg_r, d_in[7] neg_tem unused by reference score
    const float* ent     = (const float*)d_in[8];
    const float* rel     = (const float*)d_in[9];
    const float* tem     = (const float*)d_in[10];
    const float* W_ih    = (const float*)d_in[11];
    const float* W_hh    = (const float*)d_in[12];
    const float* b_ih    = (const float*)d_in[13];
    const float* b_hh    = (const float*)d_in[14];
    float* out = (float*)d_out;

    // 1) Project the TABLES (532 rows), not the batch: 38x less GEMM work.
    dim3 gproj((NPROJ + 31) / 32, G4 / 32);     // 17 x 16
    proj_kernel<<<gproj, 256>>>(W_ih, rel, tem, b_ih, b_hh);

    // 2) Step 0 (h=c=0): pure gather + activation from rel projections.
    lstm_step0_kernel<<<(BB * DD) / 256, 256>>>(pos_r);

    // 3) Steps 1..4: fused GEMM + gather + LSTM update (no gate round-trips).
    for (int t = 1; t < TT; t++)
        rec_step_kernel<<<BB / 32, 256>>>(W_hh, pos_tem, t);

    // 4) L1 scores.
    score_kernel<<<(BB * 32) / 256, 256>>>(pos_h, pos_t, neg_h, neg_t, ent, out);
}

// round 8
// speedup vs baseline: 1.4199x; 1.0033x over previous
#include <cuda_runtime.h>
#include <math.h>

#define BB 4096
#define DD 128
#define G4 512          // 4 gates * D
#define NPROJ 532       // 500 rel rows + 32 tem rows
#define ROWS 32         // batch rows per block
#define KC 8
#define NCH (DD / KC)   // 16

// Scratch (allocation-free: device global). ~1MB, L2-resident.
__device__ float g_proj[NPROJ * G4];

__device__ __forceinline__ float fast_sig(float x) {
    return 1.f / (1.f + __expf(-x));
}
__device__ __forceinline__ float fast_tanh(float x) {
    return fmaf(2.f, fast_sig(2.f * x), -1.f);
}
__device__ __forceinline__ unsigned long long pack2(float lo, float hi) {
    unsigned long long r;
    asm("mov.b64 %0, {%1, %2};" : "=l"(r) : "r"(__float_as_uint(lo)), "r"(__float_as_uint(hi)));
    return r;
}
__device__ __forceinline__ void fma2(unsigned long long& d, unsigned long long a, unsigned long long b) {
    asm("fma.rn.f32x2 %0, %1, %2, %0;" : "+l"(d) : "l"(a), "l"(b));
}
__device__ __forceinline__ float lo2(unsigned long long v) {
    return __uint_as_float((unsigned int)v);
}
__device__ __forceinline__ float hi2(unsigned long long v) {
    return __uint_as_float((unsigned int)(v >> 32));
}

// ---------------------------------------------------------------------------
// proj_kernel: g_proj[r][c] = emb_row(r) . W_ih[c] + b_ih[c] + b_hh[c]
// rows 0..499 = rel_emb, rows 500..531 = tem_emb.  ~35 MMAC.
// ---------------------------------------------------------------------------
__global__ __launch_bounds__(256) void proj_kernel(
    const float* __restrict__ W_ih,
    const float* __restrict__ rel_emb,
    const float* __restrict__ tem_emb,
    const float* __restrict__ b_ih,
    const float* __restrict__ b_hh)
{
    __shared__ float As[DD][36];
    __shared__ float Bs[DD][36];
    __shared__ const float* rowptr[32];

    const int tid = threadIdx.x;
    const int m0 = blockIdx.x * 32;
    const int n0 = blockIdx.y * 32;

    if (tid < 32) {
        int r = m0 + tid;
        if (r >= NPROJ) r = 0;
        rowptr[tid] = (r < 500) ? (rel_emb + (size_t)r * DD)
                                : (tem_emb + (size_t)(r - 500) * DD);
    }
    __syncthreads();

#pragma unroll
    for (int q = 0; q < 4; q++) {
        int f4i = tid * 4 + q;
        int row = f4i >> 5;
        int kk  = (f4i & 31) << 2;
        float4 v = *(const float4*)(rowptr[row] + kk);
        As[kk + 0][row] = v.x; As[kk + 1][row] = v.y;
        As[kk + 2][row] = v.z; As[kk + 3][row] = v.w;
    }
#pragma unroll
    for (int q = 0; q < 4; q++) {
        int f4i = tid * 4 + q;
        int col = f4i >> 5;
        int kk  = (f4i & 31) << 2;
        float4 v = *(const float4*)(W_ih + (size_t)(n0 + col) * DD + kk);
        Bs[kk + 0][col] = v.x; Bs[kk + 1][col] = v.y;
        Bs[kk + 2][col] = v.z; Bs[kk + 3][col] = v.w;
    }
    __syncthreads();

    const int ty = tid >> 4, tx = tid & 15;
    const int row0 = ty * 2, col0 = tx * 2;

    float acc[2][2] = {{0.f, 0.f}, {0.f, 0.f}};
#pragma unroll
    for (int k = 0; k < DD; k++) {
        float a0 = As[k][row0], a1 = As[k][row0 + 1];
        float2 b = *(const float2*)&Bs[k][col0];
        acc[0][0] = fmaf(a0, b.x, acc[0][0]);
        acc[0][1] = fmaf(a0, b.y, acc[0][1]);
        acc[1][0] = fmaf(a1, b.x, acc[1][0]);
        acc[1][1] = fmaf(a1, b.y, acc[1][1]);
    }

    float bia0 = b_ih[n0 + col0]     + b_hh[n0 + col0];
    float bia1 = b_ih[n0 + col0 + 1] + b_hh[n0 + col0 + 1];
#pragma unroll
    for (int r = 0; r < 2; r++) {
        int m = m0 + row0 + r;
        if (m < NPROJ) {
            float2 o = {acc[r][0] + bia0, acc[r][1] + bia1};
            *(float2*)&g_proj[(size_t)m * G4 + n0 + col0] = o;
        }
    }
}

// ---------------------------------------------------------------------------
// Fused LSTM + score kernel. grid=128 (32 rows each), block=512 (16 warps).
// Thread (ty=tid/64, tx=tid%64): rows ty*4..+3, cols j0=2tx, j0+1 (all 4 gates).
// h lives in As (transposed [d][row]) in smem; c lives in registers.
// GEMM uses packed fma.rn.f32x2 (2 MACs/instr).
// ---------------------------------------------------------------------------
__global__ __launch_bounds__(512) void lstm_fused_kernel(
    const float* __restrict__ W_hh,
    const int* __restrict__ pos_r,
    const int* __restrict__ pos_tem,
    const int* __restrict__ pos_h, const int* __restrict__ pos_t,
    const int* __restrict__ neg_h, const int* __restrict__ neg_t,
    const float* __restrict__ ent,
    float* __restrict__ out)
{
    __shared__ float As[DD][ROWS + 4];   // h transposed; overlaid by hbuf at score
    __shared__ float Bs[KC][G4 + 4];     // W_hh chunk [k][col]
    __shared__ int   trow[4][ROWS];
    __shared__ int   ridx[ROWS];

    const int tid = threadIdx.x;
    const int m0  = blockIdx.x * ROWS;
    const int tx  = tid & 63;
    const int ty  = tid >> 6;            // 0..7
    const int row0 = ty * 4;
    const int j0   = 2 * tx;

    if (tid < ROWS) {
        ridx[tid] = pos_r[m0 + tid];
#pragma unroll
        for (int t = 0; t < 4; t++)
            trow[t][tid] = 500 + pos_tem[(m0 + tid) * 4 + t];
    }
    __syncthreads();

    // ---- Step 0: h = c = 0 -> gates from rel projection; write h0 into As.
    float c0[4], c1[4];                  // c for (row0+rr, j0) and (row0+rr, j0+1)
#pragma unroll
    for (int rr = 0; rr < 4; rr++) {
        const float* p = g_proj + (size_t)ridx[row0 + rr] * G4;
        float2 pi = *(const float2*)(p + j0);
        float2 pg = *(const float2*)(p + 2 * DD + j0);
        float2 po = *(const float2*)(p + 3 * DD + j0);
        float i0 = fast_sig(pi.x),  i1 = fast_sig(pi.y);
        float g0 = fast_tanh(pg.x), g1 = fast_tanh(pg.y);
        float o0 = fast_sig(po.x),  o1 = fast_sig(po.y);
        c0[rr] = i0 * g0; c1[rr] = i1 * g1;
        As[j0    ][row0 + rr] = o0 * fast_tanh(c0[rr]);
        As[j0 + 1][row0 + rr] = o1 * fast_tanh(c1[rr]);
    }

    // First W_hh chunk, preloaded once, reused at every step (W is step-invariant).
    const float* wrow = W_hh + (size_t)tid * DD;   // thread owns column `tid`
    const float4 w0a = *(const float4*)(wrow);
    const float4 w0b = *(const float4*)(wrow + 4);

    float2 hfin0[4], hfin1[4];           // final h (step 4) per row, packed at end

    for (int t = 1; t <= 4; t++) {
        unsigned long long acc[4][4];    // acc[rr][gate] packed (j0, j0+1)
#pragma unroll
        for (int r = 0; r < 4; r++)
#pragma unroll
            for (int g = 0; g < 4; g++) acc[r][g] = 0ull;

        float4 bva = w0a, bvb = w0b;

        for (int ch = 0; ch < NCH; ch++) {
            __syncthreads();             // Bs consumed / As(h) writes visible
            Bs[0][tid] = bva.x; Bs[1][tid] = bva.y;
            Bs[2][tid] = bva.z; Bs[3][tid] = bva.w;
            Bs[4][tid] = bvb.x; Bs[5][tid] = bvb.y;
            Bs[6][tid] = bvb.z; Bs[7][tid] = bvb.w;
            __syncthreads();
            if (ch + 1 < NCH) {
                int k0 = (ch + 1) * KC;
                bva = *(const float4*)(wrow + k0);
                bvb = *(const float4*)(wrow + k0 + 4);
            }
#pragma unroll
            for (int kk = 0; kk < KC; kk++) {
                int k = ch * KC + kk;
                float4 a4 = *(const float4*)&As[k][row0];    // warp-broadcast
                unsigned long long a2[4];
                a2[0] = pack2(a4.x, a4.x);
                a2[1] = pack2(a4.y, a4.y);
                a2[2] = pack2(a4.z, a4.z);
                a2[3] = pack2(a4.w, a4.w);
#pragma unroll
                for (int g = 0; g < 4; g++) {
                    unsigned long long b2 =
                        *(const unsigned long long*)&Bs[kk][g * DD + j0];
                    fma2(acc[0][g], a2[0], b2);
                    fma2(acc[1][g], a2[1], b2);
                    fma2(acc[2][g], a2[2], b2);
                    fma2(acc[3][g], a2[3], b2);
                }
            }
        }

        // ---- Fused epilogue: + xg gather, activate, update c (regs), new h.
        float h0[4], h1[4];
#pragma unroll
        for (int rr = 0; rr < 4; rr++) {
            const float* p = g_proj + (size_t)trow[t - 1][row0 + rr] * G4;
            float2 pi = *(const float2*)(p + j0);
            float2 pf = *(const float2*)(p + DD + j0);
            float2 pg = *(const float2*)(p + 2 * DD + j0);
            float2 po = *(const float2*)(p + 3 * DD + j0);

            float i0 = fast_sig(lo2(acc[rr][0]) + pi.x);
            float i1 = fast_sig(hi2(acc[rr][0]) + pi.y);
            float f0 = fast_sig(lo2(acc[rr][1]) + pf.x);
            float f1 = fast_sig(hi2(acc[rr][1]) + pf.y);
            float g0 = fast_tanh(lo2(acc[rr][2]) + pg.x);
            float g1 = fast_tanh(hi2(acc[rr][2]) + pg.y);
            float o0 = fast_sig(lo2(acc[rr][3]) + po.x);
            float o1 = fast_sig(hi2(acc[rr][3]) + po.y);

            c0[rr] = f0 * c0[rr] + i0 * g0;
            c1[rr] = f1 * c1[rr] + i1 * g1;
            h0[rr] = o0 * fast_tanh(c0[rr]);
            h1[rr] = o1 * fast_tanh(c1[rr]);
        }

        __syncthreads();                 // all warps done reading As this step
        if (t < 4) {
#pragma unroll
            for (int rr = 0; rr < 4; rr++) {
                As[j0    ][row0 + rr] = h0[rr];
                As[j0 + 1][row0 + rr] = h1[rr];
            }
            // next iteration's first syncthreads publishes these writes
        } else {
#pragma unroll
            for (int rr = 0; rr < 4; rr++) {
                hfin0[rr] = make_float2(h0[rr], h1[rr]);
                (void)hfin1;
            }
        }
    }

    // ---- Write final h row-major into hbuf (overlays As region), then score.
    float* hbuf = &As[0][0];             // [ROWS][132] floats, fits in As (128*36)
#pragma unroll
    for (int rr = 0; rr < 4; rr++)
        *(float2*)&hbuf[(row0 + rr) * 132 + j0] = hfin0[rr];
    __syncthreads();

    const int w    = tid >> 5;           // 0..15 -> 2 rows each
    const int lane = tid & 31;
    const int d0   = lane * 4;
#pragma unroll
    for (int rsub = 0; rsub < 2; rsub++) {
        int r = w * 2 + rsub;
        int m = m0 + r;
        float4 h4 = *(const float4*)&hbuf[r * 132 + d0];
        const float4* eph = (const float4*)(ent + (size_t)pos_h[m] * DD) + lane;
        const float4* ept = (const float4*)(ent + (size_t)pos_t[m] * DD) + lane;
        const float4* enh = (const float4*)(ent + (size_t)neg_h[m] * DD) + lane;
        const float4* ent_ = (const float4*)(ent + (size_t)neg_t[m] * DD) + lane;
        float4 a = *eph, b = *ept, c = *enh, d = *ent_;
        float pos = fabsf(a.x + h4.x - b.x) + fabsf(a.y + h4.y - b.y)
                  + fabsf(a.z + h4.z - b.z) + fabsf(a.w + h4.w - b.w);
        float neg = fabsf(c.x + h4.x - d.x) + fabsf(c.y + h4.y - d.y)
                  + fabsf(c.z + h4.z - d.z) + fabsf(c.w + h4.w - d.w);
#pragma unroll
        for (int off = 16; off; off >>= 1) {
            pos += __shfl_down_sync(0xffffffffu, pos, off);
            neg += __shfl_down_sync(0xffffffffu, neg, off);
        }
        if (lane == 0) {
            out[m]      = pos;
            out[BB + m] = neg;
        }
    }
}

extern "C" void kernel_launch(void* const* d_in, const int* in_sizes, int n_in,
                              void* d_out, int out_size)
{
    (void)in_sizes; (void)n_in; (void)out_size;
    const int*   pos_h   = (const int*)d_in[0];
    const int*   pos_t   = (const int*)d_in[1];
    const int*   pos_r   = (const int*)d_in[2];
    const int*   pos_tem = (const int*)d_in[3];
    const int*   neg_h   = (const int*)d_in[4];
    const int*   neg_t   = (const int*)d_in[5];
    // d_in[6] neg_r, d_in[7] neg_tem unused by reference score
    const float* ent     = (const float*)d_in[8];
    const float* rel     = (const float*)d_in[9];
    const float* tem     = (const float*)d_in[10];
    const float* W_ih    = (const float*)d_in[11];
    const float* W_hh    = (const float*)d_in[12];
    const float* b_ih    = (const float*)d_in[13];
    const float* b_hh    = (const float*)d_in[14];
    float* out = (float*)d_out;

    // 1) Project the tables (532 rows), not the batch.
    dim3 gproj((NPROJ + 31) / 32, G4 / 32);
    proj_kernel<<<gproj, 256>>>(W_ih, rel, tem, b_ih, b_hh);

    // 2) Everything else in one fused kernel: step0 + 4 rec steps + scoring.
    lstm_fused_kernel<<<BB / ROWS, 512>>>(W_hh, pos_r, pos_tem,
                                          pos_h, pos_t, neg_h, neg_t,
                                          ent, out);
}

// round 9
// speedup vs baseline: 1.4242x; 1.0031x over previous
#include <cuda_runtime.h>
#include <math.h>

#define BB 4096
#define DD 128
#define G4 512          // 4 gates * D
#define NPROJ 532       // 500 rel rows + 32 tem rows
#define ROWS 32         // batch rows per block
#define KC 8
#define NCH (DD / KC)   // 16

// Scratch (allocation-free: device global). ~1MB, L2-resident.
__device__ float g_proj[NPROJ * G4];

__device__ __forceinline__ float fast_sig(float x) {
    return 1.f / (1.f + __expf(-x));
}
__device__ __forceinline__ float fast_tanh(float x) {
    return fmaf(2.f, fast_sig(2.f * x), -1.f);
}
__device__ __forceinline__ unsigned long long pack2(float lo, float hi) {
    unsigned long long r;
    asm("mov.b64 %0, {%1, %2};" : "=l"(r) : "r"(__float_as_uint(lo)), "r"(__float_as_uint(hi)));
    return r;
}
__device__ __forceinline__ void fma2(unsigned long long& d, unsigned long long a, unsigned long long b) {
    asm("fma.rn.f32x2 %0, %1, %2, %0;" : "+l"(d) : "l"(a), "l"(b));
}
__device__ __forceinline__ float lo2(unsigned long long v) {
    return __uint_as_float((unsigned int)v);
}
__device__ __forceinline__ float hi2(unsigned long long v) {
    return __uint_as_float((unsigned int)(v >> 32));
}

// ---------------------------------------------------------------------------
// proj_kernel: g_proj[r][c] = emb_row(r) . W_ih[c] + b_ih[c] + b_hh[c]
// rows 0..499 = rel_emb, rows 500..531 = tem_emb.  ~35 MMAC.
// ---------------------------------------------------------------------------
__global__ __launch_bounds__(256) void proj_kernel(
    const float* __restrict__ W_ih,
    const float* __restrict__ rel_emb,
    const float* __restrict__ tem_emb,
    const float* __restrict__ b_ih,
    const float* __restrict__ b_hh)
{
    __shared__ float As[DD][36];
    __shared__ float Bs[DD][36];
    __shared__ const float* rowptr[32];

    const int tid = threadIdx.x;
    const int m0 = blockIdx.x * 32;
    const int n0 = blockIdx.y * 32;

    if (tid < 32) {
        int r = m0 + tid;
        if (r >= NPROJ) r = 0;
        rowptr[tid] = (r < 500) ? (rel_emb + (size_t)r * DD)
                                : (tem_emb + (size_t)(r - 500) * DD);
    }
    __syncthreads();

#pragma unroll
    for (int q = 0; q < 4; q++) {
        int f4i = tid * 4 + q;
        int row = f4i >> 5;
        int kk  = (f4i & 31) << 2;
        float4 v = *(const float4*)(rowptr[row] + kk);
        As[kk + 0][row] = v.x; As[kk + 1][row] = v.y;
        As[kk + 2][row] = v.z; As[kk + 3][row] = v.w;
    }
#pragma unroll
    for (int q = 0; q < 4; q++) {
        int f4i = tid * 4 + q;
        int col = f4i >> 5;
        int kk  = (f4i & 31) << 2;
        float4 v = *(const float4*)(W_ih + (size_t)(n0 + col) * DD + kk);
        Bs[kk + 0][col] = v.x; Bs[kk + 1][col] = v.y;
        Bs[kk + 2][col] = v.z; Bs[kk + 3][col] = v.w;
    }
    __syncthreads();

    const int ty = tid >> 4, tx = tid & 15;
    const int row0 = ty * 2, col0 = tx * 2;

    float acc[2][2] = {{0.f, 0.f}, {0.f, 0.f}};
#pragma unroll
    for (int k = 0; k < DD; k++) {
        float a0 = As[k][row0], a1 = As[k][row0 + 1];
        float2 b = *(const float2*)&Bs[k][col0];
        acc[0][0] = fmaf(a0, b.x, acc[0][0]);
        acc[0][1] = fmaf(a0, b.y, acc[0][1]);
        acc[1][0] = fmaf(a1, b.x, acc[1][0]);
        acc[1][1] = fmaf(a1, b.y, acc[1][1]);
    }

    float bia0 = b_ih[n0 + col0]     + b_hh[n0 + col0];
    float bia1 = b_ih[n0 + col0 + 1] + b_hh[n0 + col0 + 1];
#pragma unroll
    for (int r = 0; r < 2; r++) {
        int m = m0 + row0 + r;
        if (m < NPROJ) {
            float2 o = {acc[r][0] + bia0, acc[r][1] + bia1};
            *(float2*)&g_proj[(size_t)m * G4 + n0 + col0] = o;
        }
    }
}

// ---------------------------------------------------------------------------
// Fused LSTM + score kernel. grid=128 (32 rows each), block=512 (16 warps).
// Thread (ty=tid/64, tx=tid%64): rows ty*4..+3, cols j0=2tx, j0+1 (all 4 gates).
// h lives in As (transposed [d][row]) in smem; c lives in registers.
// GEMM uses packed fma.rn.f32x2 (2 MACs/instr).
// ---------------------------------------------------------------------------
__global__ __launch_bounds__(512) void lstm_fused_kernel(
    const float* __restrict__ W_hh,
    const int* __restrict__ pos_r,
    const int* __restrict__ pos_tem,
    const int* __restrict__ pos_h, const int* __restrict__ pos_t,
    const int* __restrict__ neg_h, const int* __restrict__ neg_t,
    const float* __restrict__ ent,
    float* __restrict__ out)
{
    __shared__ float As[DD][ROWS + 4];   // h transposed; overlaid by hbuf at score
    __shared__ float Bs[KC][G4 + 4];     // W_hh chunk [k][col]
    __shared__ int   trow[4][ROWS];
    __shared__ int   ridx[ROWS];

    const int tid = threadIdx.x;
    const int m0  = blockIdx.x * ROWS;
    const int tx  = tid & 63;
    const int ty  = tid >> 6;            // 0..7
    const int row0 = ty * 4;
    const int j0   = 2 * tx;

    if (tid < ROWS) {
        ridx[tid] = pos_r[m0 + tid];
#pragma unroll
        for (int t = 0; t < 4; t++)
            trow[t][tid] = 500 + pos_tem[(m0 + tid) * 4 + t];
    }
    __syncthreads();

    // ---- Step 0: h = c = 0 -> gates from rel projection; write h0 into As.
    float c0[4], c1[4];                  // c for (row0+rr, j0) and (row0+rr, j0+1)
#pragma unroll
    for (int rr = 0; rr < 4; rr++) {
        const float* p = g_proj + (size_t)ridx[row0 + rr] * G4;
        float2 pi = *(const float2*)(p + j0);
        float2 pg = *(const float2*)(p + 2 * DD + j0);
        float2 po = *(const float2*)(p + 3 * DD + j0);
        float i0 = fast_sig(pi.x),  i1 = fast_sig(pi.y);
        float g0 = fast_tanh(pg.x), g1 = fast_tanh(pg.y);
        float o0 = fast_sig(po.x),  o1 = fast_sig(po.y);
        c0[rr] = i0 * g0; c1[rr] = i1 * g1;
        As[j0    ][row0 + rr] = o0 * fast_tanh(c0[rr]);
        As[j0 + 1][row0 + rr] = o1 * fast_tanh(c1[rr]);
    }

    // First W_hh chunk, preloaded once, reused at every step (W is step-invariant).
    const float* wrow = W_hh + (size_t)tid * DD;   // thread owns column `tid`
    const float4 w0a = *(const float4*)(wrow);
    const float4 w0b = *(const float4*)(wrow + 4);

    float2 hfin0[4], hfin1[4];           // final h (step 4) per row, packed at end

    for (int t = 1; t <= 4; t++) {
        unsigned long long acc[4][4];    // acc[rr][gate] packed (j0, j0+1)
#pragma unroll
        for (int r = 0; r < 4; r++)
#pragma unroll
            for (int g = 0; g < 4; g++) acc[r][g] = 0ull;

        float4 bva = w0a, bvb = w0b;

        for (int ch = 0; ch < NCH; ch++) {
            __syncthreads();             // Bs consumed / As(h) writes visible
            Bs[0][tid] = bva.x; Bs[1][tid] = bva.y;
            Bs[2][tid] = bva.z; Bs[3][tid] = bva.w;
            Bs[4][tid] = bvb.x; Bs[5][tid] = bvb.y;
            Bs[6][tid] = bvb.z; Bs[7][tid] = bvb.w;
            __syncthreads();
            if (ch + 1 < NCH) {
                int k0 = (ch + 1) * KC;
                bva = *(const float4*)(wrow + k0);
                bvb = *(const float4*)(wrow + k0 + 4);
            }
#pragma unroll
            for (int kk = 0; kk < KC; kk++) {
                int k = ch * KC + kk;
                float4 a4 = *(const float4*)&As[k][row0];    // warp-broadcast
                unsigned long long a2[4];
                a2[0] = pack2(a4.x, a4.x);
                a2[1] = pack2(a4.y, a4.y);
                a2[2] = pack2(a4.z, a4.z);
                a2[3] = pack2(a4.w, a4.w);
#pragma unroll
                for (int g = 0; g < 4; g++) {
                    unsigned long long b2 =
                        *(const unsigned long long*)&Bs[kk][g * DD + j0];
                    fma2(acc[0][g], a2[0], b2);
                    fma2(acc[1][g], a2[1], b2);
                    fma2(acc[2][g], a2[2], b2);
                    fma2(acc[3][g], a2[3], b2);
                }
            }
        }

        // ---- Fused epilogue: + xg gather, activate, update c (regs), new h.
        float h0[4], h1[4];
#pragma unroll
        for (int rr = 0; rr < 4; rr++) {
            const float* p = g_proj + (size_t)trow[t - 1][row0 + rr] * G4;
            float2 pi = *(const float2*)(p + j0);
            float2 pf = *(const float2*)(p + DD + j0);
            float2 pg = *(const float2*)(p + 2 * DD + j0);
            float2 po = *(const float2*)(p + 3 * DD + j0);

            float i0 = fast_sig(lo2(acc[rr][0]) + pi.x);
            float i1 = fast_sig(hi2(acc[rr][0]) + pi.y);
            float f0 = fast_sig(lo2(acc[rr][1]) + pf.x);
            float f1 = fast_sig(hi2(acc[rr][1]) + pf.y);
            float g0 = fast_tanh(lo2(acc[rr][2]) + pg.x);
            float g1 = fast_tanh(hi2(acc[rr][2]) + pg.y);
            float o0 = fast_sig(lo2(acc[rr][3]) + po.x);
            float o1 = fast_sig(hi2(acc[rr][3]) + po.y);

            c0[rr] = f0 * c0[rr] + i0 * g0;
            c1[rr] = f1 * c1[rr] + i1 * g1;
            h0[rr] = o0 * fast_tanh(c0[rr]);
            h1[rr] = o1 * fast_tanh(c1[rr]);
        }

        __syncthreads();                 // all warps done reading As this step
        if (t < 4) {
#pragma unroll
            for (int rr = 0; rr < 4; rr++) {
                As[j0    ][row0 + rr] = h0[rr];
                As[j0 + 1][row0 + rr] = h1[rr];
            }
            // next iteration's first syncthreads publishes these writes
        } else {
#pragma unroll
            for (int rr = 0; rr < 4; rr++) {
                hfin0[rr] = make_float2(h0[rr], h1[rr]);
                (void)hfin1;
            }
        }
    }

    // ---- Write final h row-major into hbuf (overlays As region), then score.
    float* hbuf = &As[0][0];             // [ROWS][132] floats, fits in As (128*36)
#pragma unroll
    for (int rr = 0; rr < 4; rr++)
        *(float2*)&hbuf[(row0 + rr) * 132 + j0] = hfin0[rr];
    __syncthreads();

    const int w    = tid >> 5;           // 0..15 -> 2 rows each
    const int lane = tid & 31;
    const int d0   = lane * 4;
#pragma unroll
    for (int rsub = 0; rsub < 2; rsub++) {
        int r = w * 2 + rsub;
        int m = m0 + r;
        float4 h4 = *(const float4*)&hbuf[r * 132 + d0];
        const float4* eph = (const float4*)(ent + (size_t)pos_h[m] * DD) + lane;
        const float4* ept = (const float4*)(ent + (size_t)pos_t[m] * DD) + lane;
        const float4* enh = (const float4*)(ent + (size_t)neg_h[m] * DD) + lane;
        const float4* ent_ = (const float4*)(ent + (size_t)neg_t[m] * DD) + lane;
        float4 a = *eph, b = *ept, c = *enh, d = *ent_;
        float pos = fabsf(a.x + h4.x - b.x) + fabsf(a.y + h4.y - b.y)
                  + fabsf(a.z + h4.z - b.z) + fabsf(a.w + h4.w - b.w);
        float neg = fabsf(c.x + h4.x - d.x) + fabsf(c.y + h4.y - d.y)
                  + fabsf(c.z + h4.z - d.z) + fabsf(c.w + h4.w - d.w);
#pragma unroll
        for (int off = 16; off; off >>= 1) {
            pos += __shfl_down_sync(0xffffffffu, pos, off);
            neg += __shfl_down_sync(0xffffffffu, neg, off);
        }
        if (lane == 0) {
            out[m]      = pos;
            out[BB + m] = neg;
        }
    }
}

extern "C" void kernel_launch(void* const* d_in, const int* in_sizes, int n_in,
                              void* d_out, int out_size)
{
    (void)in_sizes; (void)n_in; (void)out_size;
    const int*   pos_h   = (const int*)d_in[0];
    const int*   pos_t   = (const int*)d_in[1];
    const int*   pos_r   = (const int*)d_in[2];
    const int*   pos_tem = (const int*)d_in[3];
    const int*   neg_h   = (const int*)d_in[4];
    const int*   neg_t   = (const int*)d_in[5];
    // d_in[6] neg_r, d_in[7] neg_tem unused by reference score
    const float* ent     = (const float*)d_in[8];
    const float* rel     = (const float*)d_in[9];
    const float* tem     = (const float*)d_in[10];
    const float* W_ih    = (const float*)d_in[11];
    const float* W_hh    = (const float*)d_in[12];
    const float* b_ih    = (const float*)d_in[13];
    const float* b_hh    = (const float*)d_in[14];
    float* out = (float*)d_out;

    // 1) Project the tables (532 rows), not the batch.
    dim3 gproj((NPROJ + 31) / 32, G4 / 32);
    proj_kernel<<<gproj, 256>>>(W_ih, rel, tem, b_ih, b_hh);

    // 2) Everything else in one fused kernel: step0 + 4 rec steps + scoring.
    lstm_fused_kernel<<<BB / ROWS, 512>>>(W_hh, pos_r, pos_tem,
                                          pos_h, pos_t, neg_h, neg_t,
                                          ent, out);
}